// round 3
// baseline (speedup 1.0000x reference)
#include <cuda_runtime.h>
#include <math.h>

#define B_   2
#define H_   8
#define NQ_  2048
#define NK_  2048
#define DM_  512
#define HD_  64
#define SCALE_ 0.125f
#define PAD  65

// Scratch (allocation-free rule: __device__ globals)
__device__ float g_Q[B_*H_*NQ_*HD_];
__device__ float g_K[B_*H_*NK_*HD_];
__device__ float g_V[B_*H_*NK_*HD_];
__device__ float g_diag[B_*H_*NK_];

// ---------------------------------------------------------------------------
// Projection: out[b][h][n][d] = X[b*N+n] . W[j] + bias[j],  j = h*64+d
// grid (DM/64, B*N/64, 3); block 256 (16x16, 4x4 microtile)
// ---------------------------------------------------------------------------
__global__ __launch_bounds__(256) void proj_kernel(
    const float* __restrict__ q, const float* __restrict__ k,
    const float* __restrict__ v,
    const float* __restrict__ Wq, const float* __restrict__ bq,
    const float* __restrict__ Wk, const float* __restrict__ bk,
    const float* __restrict__ Wv, const float* __restrict__ bv)
{
    __shared__ float As[64][PAD];
    __shared__ float Bs[64][PAD];

    const float *X, *W, *bias;
    float* outp;
    if (blockIdx.z == 0)      { X = q; W = Wq; bias = bq; outp = g_Q; }
    else if (blockIdx.z == 1) { X = k; W = Wk; bias = bk; outp = g_K; }
    else                      { X = v; W = Wv; bias = bv; outp = g_V; }

    const int tid = threadIdx.x;
    const int tx = tid & 15, ty = tid >> 4;
    const int row0 = blockIdx.y * 64;
    const int col0 = blockIdx.x * 64;

    float acc[4][4];
    #pragma unroll
    for (int i = 0; i < 4; i++)
        #pragma unroll
        for (int j = 0; j < 4; j++) acc[i][j] = 0.f;

    for (int kc = 0; kc < DM_; kc += 64) {
        #pragma unroll
        for (int u = 0; u < 4; u++) {
            int idx = tid + u * 256;             // 0..1023
            int r   = idx >> 4;
            int c4  = (idx & 15) << 2;
            float4 xv = *(const float4*)(X + (size_t)(row0 + r) * DM_ + kc + c4);
            As[r][c4+0] = xv.x; As[r][c4+1] = xv.y; As[r][c4+2] = xv.z; As[r][c4+3] = xv.w;
            float4 wv = *(const float4*)(W + (size_t)(col0 + r) * DM_ + kc + c4);
            Bs[r][c4+0] = wv.x; Bs[r][c4+1] = wv.y; Bs[r][c4+2] = wv.z; Bs[r][c4+3] = wv.w;
        }
        __syncthreads();
        #pragma unroll 16
        for (int kk = 0; kk < 64; kk++) {
            float a[4], bb[4];
            #pragma unroll
            for (int i = 0; i < 4; i++) a[i]  = As[ty*4+i][kk];
            #pragma unroll
            for (int j = 0; j < 4; j++) bb[j] = Bs[tx*4+j][kk];
            #pragma unroll
            for (int i = 0; i < 4; i++)
                #pragma unroll
                for (int j = 0; j < 4; j++)
                    acc[i][j] = fmaf(a[i], bb[j], acc[i][j]);
        }
        __syncthreads();
    }

    #pragma unroll
    for (int i = 0; i < 4; i++) {
        int r = row0 + ty*4 + i;
        int b = r >> 11;          // /2048
        int n = r & 2047;
        #pragma unroll
        for (int j = 0; j < 4; j++) {
            int jj = col0 + tx*4 + j;
            int h = jj >> 6, d = jj & 63;
            outp[(((size_t)(b*H_ + h) * NQ_) + n) * HD_ + d] = acc[i][j] + bias[jj];
        }
    }
}

// ---------------------------------------------------------------------------
// diag[b][h][k] = pearson[b][h][k][k]
// ---------------------------------------------------------------------------
__global__ void diag_kernel(const float* __restrict__ pearson)
{
    int idx = blockIdx.x * 256 + threadIdx.x;
    if (idx < B_*H_*NK_) {
        int k  = idx & (NK_ - 1);
        int bh = idx >> 11;
        g_diag[idx] = pearson[((size_t)bh * NK_ + k) * NK_ + k];
    }
}

// ---------------------------------------------------------------------------
// Fused flash-style attention per (b,h): 64 q-rows per block.
// Online softmax with unmasked denominator; mask*diag applied to accumulator.
// grid (NQ/64, H, B); block 256; dynamic smem 67328 B.
// ---------------------------------------------------------------------------
__global__ __launch_bounds__(256) void attn_kernel(
    const float* __restrict__ mask, float* __restrict__ out)
{
    extern __shared__ float sm[];
    float* Qs   = sm;                 // 64*PAD
    float* Ks   = Qs + 64*PAD;        // 64*PAD
    float* Vs   = Ks + 64*PAD;        // 64*PAD
    float* Ps   = Vs + 64*PAD;        // 64*PAD (S, then P)
    float* mrow = Ps + 64*PAD;        // 64
    float* lrow = mrow + 64;          // 64
    float* rsc  = lrow + 64;          // 64

    const int tid  = threadIdx.x;
    const int tx   = tid & 15, ty = tid >> 4;
    const int lane = tid & 31, warp = tid >> 5;
    const int q0 = blockIdx.x * 64;
    const int h  = blockIdx.y;
    const int b  = blockIdx.z;
    const int bh = b * H_ + h;

    const float* Qg = g_Q + (size_t)bh * NQ_ * HD_ + (size_t)q0 * HD_;
    const float* Kg = g_K + (size_t)bh * NK_ * HD_;
    const float* Vg = g_V + (size_t)bh * NK_ * HD_;
    const float* dg = g_diag + (size_t)bh * NK_;
    const float* mg = mask + ((size_t)bh * NQ_ + q0) * NK_;

    // Load Q tile
    #pragma unroll
    for (int u = 0; u < 4; u++) {
        int idx = tid + u * 256;
        int r = idx >> 4, c4 = (idx & 15) << 2;
        float4 qv = *(const float4*)(Qg + (size_t)r * HD_ + c4);
        Qs[r*PAD + c4+0] = qv.x; Qs[r*PAD + c4+1] = qv.y;
        Qs[r*PAD + c4+2] = qv.z; Qs[r*PAD + c4+3] = qv.w;
    }
    if (tid < 64) { mrow[tid] = -1e30f; lrow[tid] = 0.f; }

    float acc[4][4];
    #pragma unroll
    for (int i = 0; i < 4; i++)
        #pragma unroll
        for (int j = 0; j < 4; j++) acc[i][j] = 0.f;

    __syncthreads();

    for (int kt = 0; kt < NK_ / 64; kt++) {
        const float* Kt = Kg + (size_t)kt * 64 * HD_;
        const float* Vt = Vg + (size_t)kt * 64 * HD_;

        // Load K & V tiles
        #pragma unroll
        for (int u = 0; u < 4; u++) {
            int idx = tid + u * 256;
            int r = idx >> 4, c4 = (idx & 15) << 2;
            float4 kv = *(const float4*)(Kt + (size_t)r * HD_ + c4);
            Ks[r*PAD + c4+0] = kv.x; Ks[r*PAD + c4+1] = kv.y;
            Ks[r*PAD + c4+2] = kv.z; Ks[r*PAD + c4+3] = kv.w;
            float4 vv = *(const float4*)(Vt + (size_t)r * HD_ + c4);
            Vs[r*PAD + c4+0] = vv.x; Vs[r*PAD + c4+1] = vv.y;
            Vs[r*PAD + c4+2] = vv.z; Vs[r*PAD + c4+3] = vv.w;
        }
        __syncthreads();

        // S = Q @ K^T  -> Ps (raw, scaling applied in softmax)
        {
            float s[4][4];
            #pragma unroll
            for (int i = 0; i < 4; i++)
                #pragma unroll
                for (int j = 0; j < 4; j++) s[i][j] = 0.f;
            #pragma unroll 8
            for (int kk = 0; kk < 64; kk++) {
                float a[4], bb[4];
                #pragma unroll
                for (int i = 0; i < 4; i++) a[i]  = Qs[(ty*4+i)*PAD + kk];
                #pragma unroll
                for (int j = 0; j < 4; j++) bb[j] = Ks[(tx*4+j)*PAD + kk];
                #pragma unroll
                for (int i = 0; i < 4; i++)
                    #pragma unroll
                    for (int j = 0; j < 4; j++)
                        s[i][j] = fmaf(a[i], bb[j], s[i][j]);
            }
            #pragma unroll
            for (int i = 0; i < 4; i++)
                #pragma unroll
                for (int j = 0; j < 4; j++)
                    Ps[(ty*4+i)*PAD + tx*4+j] = s[i][j];
        }
        __syncthreads();

        // Online softmax on 8 rows per warp; apply mask*diag to P
        {
            float d0 = dg[kt*64 + lane];
            float d1 = dg[kt*64 + 32 + lane];
            float mk0[8], mk1[8];
            #pragma unroll
            for (int i = 0; i < 8; i++) {
                const float* mr = mg + (size_t)(warp*8 + i) * NK_ + kt*64;
                mk0[i] = mr[lane];
                mk1[i] = mr[lane + 32];
            }
            #pragma unroll
            for (int i = 0; i < 8; i++) {
                int r = warp*8 + i;
                float v0 = Ps[r*PAD + lane]      * SCALE_;
                float v1 = Ps[r*PAD + lane + 32] * SCALE_;
                float tmax = fmaxf(v0, v1);
                #pragma unroll
                for (int off = 16; off > 0; off >>= 1)
                    tmax = fmaxf(tmax, __shfl_xor_sync(0xffffffffu, tmax, off));
                float mold = mrow[r];
                float newm = fmaxf(mold, tmax);
                float f  = __expf(mold - newm);
                float e0 = __expf(v0 - newm);
                float e1 = __expf(v1 - newm);
                float ts = e0 + e1;
                #pragma unroll
                for (int off = 16; off > 0; off >>= 1)
                    ts += __shfl_xor_sync(0xffffffffu, ts, off);
                if (lane == 0) {
                    lrow[r] = lrow[r] * f + ts;
                    mrow[r] = newm;
                    rsc[r]  = f;
                }
                Ps[r*PAD + lane]      = e0 * mk0[i] * d0;
                Ps[r*PAD + lane + 32] = e1 * mk1[i] * d1;
            }
        }
        __syncthreads();

        // Rescale acc, then acc += P @ V
        {
            float fr[4];
            #pragma unroll
            for (int i = 0; i < 4; i++) fr[i] = rsc[ty*4+i];
            #pragma unroll
            for (int i = 0; i < 4; i++)
                #pragma unroll
                for (int j = 0; j < 4; j++) acc[i][j] *= fr[i];

            #pragma unroll 8
            for (int kk = 0; kk < 64; kk++) {
                float a[4], bb[4];
                #pragma unroll
                for (int i = 0; i < 4; i++) a[i]  = Ps[(ty*4+i)*PAD + kk];
                #pragma unroll
                for (int j = 0; j < 4; j++) bb[j] = Vs[kk*PAD + tx*4+j];
                #pragma unroll
                for (int i = 0; i < 4; i++)
                    #pragma unroll
                    for (int j = 0; j < 4; j++)
                        acc[i][j] = fmaf(a[i], bb[j], acc[i][j]);
            }
        }
        __syncthreads();
    }

    // O = acc / l, write to out[b][q][h*64+d]
    #pragma unroll
    for (int i = 0; i < 4; i++) {
        int r = ty*4 + i;
        float inv = 1.f / lrow[r];
        #pragma unroll
        for (int j = 0; j < 4; j++) {
            int c = tx*4 + j;
            out[((size_t)b * NQ_ + q0 + r) * DM_ + h * HD_ + c] = acc[i][j] * inv;
        }
    }
}

// ---------------------------------------------------------------------------
#define ATTN_SMEM ((4*64*PAD + 3*64) * (int)sizeof(float))

extern "C" void kernel_launch(void* const* d_in, const int* in_sizes, int n_in,
                              void* d_out, int out_size)
{
    const float* q       = (const float*)d_in[0];
    const float* k       = (const float*)d_in[1];
    const float* v       = (const float*)d_in[2];
    const float* mask    = (const float*)d_in[3];
    const float* pearson = (const float*)d_in[4];
    const float* Wq      = (const float*)d_in[5];
    const float* bq      = (const float*)d_in[6];
    const float* Wk      = (const float*)d_in[7];
    const float* bk      = (const float*)d_in[8];
    const float* Wv      = (const float*)d_in[9];
    const float* bv      = (const float*)d_in[10];
    float* out = (float*)d_out;

    cudaFuncSetAttribute(attn_kernel,
                         cudaFuncAttributeMaxDynamicSharedMemorySize, ATTN_SMEM);

    dim3 pg(DM_/64, (B_*NQ_)/64, 3);
    proj_kernel<<<pg, 256>>>(q, k, v, Wq, bq, Wk, bk, Wv, bv);

    diag_kernel<<<(B_*H_*NK_ + 255)/256, 256>>>(pearson);

    dim3 ag(NQ_/64, H_, B_);
    attn_kernel<<<ag, 256, ATTN_SMEM>>>(mask, out);
}

// round 4
// speedup vs baseline: 3.3278x; 3.3278x over previous
#include <cuda_runtime.h>
#include <math.h>

#define B_   2
#define H_   8
#define NQ_  2048
#define NK_  2048
#define DM_  512
#define HD_  64
#define SCALE_ 0.125f

#define KSTRIDE 68   // 68 % 32 == 4 : conflict-free for 8-row x 4-col frag reads
#define VSTRIDE 72   // 72 % 32 == 8 : conflict-free for 4-row x 8-col frag reads
#define PSTRIDE 68

// Scratch (allocation-free rule: __device__ globals)
__device__ float g_Q[B_*H_*NQ_*HD_];
__device__ float g_K[B_*H_*NK_*HD_];
__device__ float g_V[B_*H_*NK_*HD_];
__device__ float g_diag[B_*H_*NK_];

// ---------------------------------------------------------------------------
// helpers
// ---------------------------------------------------------------------------
__device__ __forceinline__ unsigned f2tf(float f) {
    unsigned u;
    asm("cvt.rna.tf32.f32 %0, %1;" : "=r"(u) : "f"(f));
    return u;
}

__device__ __forceinline__ void mma_tf32(float c[4], const unsigned a[4],
                                         unsigned b0, unsigned b1) {
    asm volatile(
        "mma.sync.aligned.m16n8k8.row.col.f32.tf32.tf32.f32 "
        "{%0,%1,%2,%3}, {%4,%5,%6,%7}, {%8,%9}, {%0,%1,%2,%3};\n"
        : "+f"(c[0]), "+f"(c[1]), "+f"(c[2]), "+f"(c[3])
        : "r"(a[0]), "r"(a[1]), "r"(a[2]), "r"(a[3]), "r"(b0), "r"(b1));
}

// ---------------------------------------------------------------------------
// Projection via tf32 MMA: out[b][h][n][d] = X[b*N+n].W[j] + bias[j], j=h*64+d
// grid (DM/64, B*N/128, 3); block 256 (8 warps, each 16 output rows)
// ---------------------------------------------------------------------------
__global__ __launch_bounds__(256) void proj_kernel(
    const float* __restrict__ q, const float* __restrict__ k,
    const float* __restrict__ v,
    const float* __restrict__ Wq, const float* __restrict__ bq,
    const float* __restrict__ Wk, const float* __restrict__ bk,
    const float* __restrict__ Wv, const float* __restrict__ bv)
{
    extern __shared__ float sm[];
    float* Xs = sm;                   // 128 x KSTRIDE
    float* Ws = Xs + 128*KSTRIDE;     // 64  x KSTRIDE

    const float *X, *W, *bias;
    float* outp;
    if (blockIdx.z == 0)      { X = q; W = Wq; bias = bq; outp = g_Q; }
    else if (blockIdx.z == 1) { X = k; W = Wk; bias = bk; outp = g_K; }
    else                      { X = v; W = Wv; bias = bv; outp = g_V; }

    const int tid  = threadIdx.x;
    const int lane = tid & 31, warp = tid >> 5;
    const int lq = lane >> 2, lr = lane & 3;
    const int m0 = warp * 16;
    const int row0 = blockIdx.y * 128;
    const int col0 = blockIdx.x * 64;

    float acc[8][4];
    #pragma unroll
    for (int j = 0; j < 8; j++)
        #pragma unroll
        for (int i = 0; i < 4; i++) acc[j][i] = 0.f;

    for (int kc = 0; kc < DM_; kc += 64) {
        // stage X tile (128x64) and W tile (64x64), converting to tf32
        #pragma unroll
        for (int it = 0; it < 8; it++) {
            int idx = tid + it * 256;
            int r = idx >> 4, c4 = (idx & 15) << 2;
            float4 xv = *(const float4*)(X + (size_t)(row0 + r) * DM_ + kc + c4);
            Xs[r*KSTRIDE + c4+0] = __uint_as_float(f2tf(xv.x));
            Xs[r*KSTRIDE + c4+1] = __uint_as_float(f2tf(xv.y));
            Xs[r*KSTRIDE + c4+2] = __uint_as_float(f2tf(xv.z));
            Xs[r*KSTRIDE + c4+3] = __uint_as_float(f2tf(xv.w));
        }
        #pragma unroll
        for (int it = 0; it < 4; it++) {
            int idx = tid + it * 256;
            int n = idx >> 4, c4 = (idx & 15) << 2;
            float4 wv = *(const float4*)(W + (size_t)(col0 + n) * DM_ + kc + c4);
            Ws[n*KSTRIDE + c4+0] = __uint_as_float(f2tf(wv.x));
            Ws[n*KSTRIDE + c4+1] = __uint_as_float(f2tf(wv.y));
            Ws[n*KSTRIDE + c4+2] = __uint_as_float(f2tf(wv.z));
            Ws[n*KSTRIDE + c4+3] = __uint_as_float(f2tf(wv.w));
        }
        __syncthreads();

        #pragma unroll
        for (int kk = 0; kk < 8; kk++) {
            unsigned a[4];
            int ab = (m0 + lq)*KSTRIDE + kk*8 + lr;
            a[0] = __float_as_uint(Xs[ab]);
            a[1] = __float_as_uint(Xs[ab + 8*KSTRIDE]);
            a[2] = __float_as_uint(Xs[ab + 4]);
            a[3] = __float_as_uint(Xs[ab + 8*KSTRIDE + 4]);
            #pragma unroll
            for (int j = 0; j < 8; j++) {
                int bb = (j*8 + lq)*KSTRIDE + kk*8 + lr;
                unsigned b0 = __float_as_uint(Ws[bb]);
                unsigned b1 = __float_as_uint(Ws[bb + 4]);
                mma_tf32(acc[j], a, b0, b1);
            }
        }
        __syncthreads();
    }

    // epilogue: bias + scatter to head-major
    const int r0g = row0 + m0 + lq;
    const int r1g = r0g + 8;
    #pragma unroll
    for (int j = 0; j < 8; j++) {
        int jj = col0 + j*8 + 2*lr;
        float2 bs = *(const float2*)(bias + jj);
        int h = jj >> 6, d = jj & 63;
        {
            int b = r0g >> 11, n = r0g & 2047;
            float* p = outp + (((size_t)(b*H_ + h) * NQ_) + n) * HD_ + d;
            float2 o; o.x = acc[j][0] + bs.x; o.y = acc[j][1] + bs.y;
            *(float2*)p = o;
        }
        {
            int b = r1g >> 11, n = r1g & 2047;
            float* p = outp + (((size_t)(b*H_ + h) * NQ_) + n) * HD_ + d;
            float2 o; o.x = acc[j][2] + bs.x; o.y = acc[j][3] + bs.y;
            *(float2*)p = o;
        }
    }
}

// ---------------------------------------------------------------------------
// diag[b][h][k] = pearson[b][h][k][k]
// ---------------------------------------------------------------------------
__global__ void diag_kernel(const float* __restrict__ pearson)
{
    int idx = blockIdx.x * 256 + threadIdx.x;
    if (idx < B_*H_*NK_) {
        int k  = idx & (NK_ - 1);
        int bh = idx >> 11;
        g_diag[idx] = pearson[((size_t)bh * NK_ + k) * NK_ + k];
    }
}

// ---------------------------------------------------------------------------
// Fused flash attention, tf32 tensor-core MMA.
// Block: 256 threads (8 warps), 128 q-rows, 64-key tiles.
// Per warp: 16 q-rows; Q frags persistent in registers; softmax in-register
// on C-fragments; P round-trips per-warp smem strip for A-frag relayout.
// grid (NQ/128, H, B)
// ---------------------------------------------------------------------------
__global__ __launch_bounds__(256) void attn_kernel(
    const float* __restrict__ mask, float* __restrict__ out)
{
    extern __shared__ float sm[];
    float* Ks = sm;                    // 64 x KSTRIDE  (K[n][d], tf32 bits)
    float* Vs = Ks + 64*KSTRIDE;       // 64 x VSTRIDE  (V[k][d], tf32 bits)
    float* Ps = Vs + 64*VSTRIDE;       // 128 x PSTRIDE (Q staging, then P)
    float* ds = Ps + 128*PSTRIDE;      // 64  (diag tile)

    const int tid  = threadIdx.x;
    const int lane = tid & 31, warp = tid >> 5;
    const int lq = lane >> 2, lr = lane & 3;
    const int m0 = warp * 16;
    const int q0 = blockIdx.x * 128;
    const int h  = blockIdx.y;
    const int b  = blockIdx.z;
    const int bh = b * H_ + h;

    const float* Qg = g_Q + (size_t)bh * NQ_ * HD_ + (size_t)q0 * HD_;
    const float* Kg = g_K + (size_t)bh * NK_ * HD_;
    const float* Vg = g_V + (size_t)bh * NK_ * HD_;
    const float* dg = g_diag + (size_t)bh * NK_;
    const float* mgbase = mask + ((size_t)bh * NQ_ + q0) * NK_;

    // ---- stage Q tile into Ps, extract persistent A-fragments ----
    #pragma unroll
    for (int it = 0; it < 8; it++) {
        int idx = tid + it * 256;
        int r = idx >> 4, c4 = (idx & 15) << 2;
        float4 qv = *(const float4*)(Qg + (size_t)r * HD_ + c4);
        Ps[r*PSTRIDE + c4+0] = __uint_as_float(f2tf(qv.x));
        Ps[r*PSTRIDE + c4+1] = __uint_as_float(f2tf(qv.y));
        Ps[r*PSTRIDE + c4+2] = __uint_as_float(f2tf(qv.z));
        Ps[r*PSTRIDE + c4+3] = __uint_as_float(f2tf(qv.w));
    }
    __syncthreads();

    unsigned qf[8][4];
    #pragma unroll
    for (int k = 0; k < 8; k++) {
        int ab = (m0 + lq)*PSTRIDE + k*8 + lr;
        qf[k][0] = __float_as_uint(Ps[ab]);
        qf[k][1] = __float_as_uint(Ps[ab + 8*PSTRIDE]);
        qf[k][2] = __float_as_uint(Ps[ab + 4]);
        qf[k][3] = __float_as_uint(Ps[ab + 8*PSTRIDE + 4]);
    }
    // (frags read only this warp's own 16-row strip; P writes below are also
    //  warp-private, so no extra block sync needed here)

    float mrow0 = -1e30f, mrow1 = -1e30f;
    float lrow0 = 0.f,   lrow1 = 0.f;
    float oacc[8][4];
    #pragma unroll
    for (int j = 0; j < 8; j++)
        #pragma unroll
        for (int i = 0; i < 4; i++) oacc[j][i] = 0.f;

    const float* mr0 = mgbase + (size_t)(m0 + lq) * NK_;
    const float* mr1 = mr0 + (size_t)8 * NK_;

    for (int kt = 0; kt < NK_/64; kt++) {
        __syncthreads();   // guard Ks/Vs reuse vs previous iteration's reads

        const float* Kt = Kg + (size_t)kt * 64 * HD_;
        const float* Vt = Vg + (size_t)kt * 64 * HD_;
        #pragma unroll
        for (int it = 0; it < 4; it++) {
            int idx = tid + it * 256;
            int n = idx >> 4, c4 = (idx & 15) << 2;
            float4 kv = *(const float4*)(Kt + (size_t)n * HD_ + c4);
            Ks[n*KSTRIDE + c4+0] = __uint_as_float(f2tf(kv.x));
            Ks[n*KSTRIDE + c4+1] = __uint_as_float(f2tf(kv.y));
            Ks[n*KSTRIDE + c4+2] = __uint_as_float(f2tf(kv.z));
            Ks[n*KSTRIDE + c4+3] = __uint_as_float(f2tf(kv.w));
            float4 vv = *(const float4*)(Vt + (size_t)n * HD_ + c4);
            Vs[n*VSTRIDE + c4+0] = __uint_as_float(f2tf(vv.x));
            Vs[n*VSTRIDE + c4+1] = __uint_as_float(f2tf(vv.y));
            Vs[n*VSTRIDE + c4+2] = __uint_as_float(f2tf(vv.z));
            Vs[n*VSTRIDE + c4+3] = __uint_as_float(f2tf(vv.w));
        }
        if (tid < 16) ((float4*)ds)[tid] = ((const float4*)(dg + kt*64))[tid];
        __syncthreads();

        // ---- S = Q @ K^T (tf32 MMA) ----
        float sacc[8][4];
        #pragma unroll
        for (int j = 0; j < 8; j++)
            #pragma unroll
            for (int i = 0; i < 4; i++) sacc[j][i] = 0.f;

        #pragma unroll
        for (int k = 0; k < 8; k++) {
            #pragma unroll
            for (int j = 0; j < 8; j++) {
                int bb = (j*8 + lq)*KSTRIDE + k*8 + lr;
                unsigned b0 = __float_as_uint(Ks[bb]);
                unsigned b1 = __float_as_uint(Ks[bb + 4]);
                mma_tf32(sacc[j], qf[k], b0, b1);
            }
        }

        // ---- in-register online softmax on C-fragments ----
        #pragma unroll
        for (int j = 0; j < 8; j++)
            #pragma unroll
            for (int i = 0; i < 4; i++) sacc[j][i] *= SCALE_;

        float rmax0 = -1e30f, rmax1 = -1e30f;
        #pragma unroll
        for (int j = 0; j < 8; j++) {
            rmax0 = fmaxf(rmax0, fmaxf(sacc[j][0], sacc[j][1]));
            rmax1 = fmaxf(rmax1, fmaxf(sacc[j][2], sacc[j][3]));
        }
        rmax0 = fmaxf(rmax0, __shfl_xor_sync(0xffffffffu, rmax0, 1));
        rmax0 = fmaxf(rmax0, __shfl_xor_sync(0xffffffffu, rmax0, 2));
        rmax1 = fmaxf(rmax1, __shfl_xor_sync(0xffffffffu, rmax1, 1));
        rmax1 = fmaxf(rmax1, __shfl_xor_sync(0xffffffffu, rmax1, 2));

        float newm0 = fmaxf(mrow0, rmax0);
        float newm1 = fmaxf(mrow1, rmax1);
        float f0 = __expf(mrow0 - newm0);
        float f1 = __expf(mrow1 - newm1);
        mrow0 = newm0; mrow1 = newm1;

        float ts0 = 0.f, ts1 = 0.f;
        #pragma unroll
        for (int j = 0; j < 8; j++) {
            sacc[j][0] = __expf(sacc[j][0] - newm0);
            sacc[j][1] = __expf(sacc[j][1] - newm0);
            sacc[j][2] = __expf(sacc[j][2] - newm1);
            sacc[j][3] = __expf(sacc[j][3] - newm1);
            ts0 += sacc[j][0] + sacc[j][1];
            ts1 += sacc[j][2] + sacc[j][3];
        }
        ts0 += __shfl_xor_sync(0xffffffffu, ts0, 1);
        ts0 += __shfl_xor_sync(0xffffffffu, ts0, 2);
        ts1 += __shfl_xor_sync(0xffffffffu, ts1, 1);
        ts1 += __shfl_xor_sync(0xffffffffu, ts1, 2);
        lrow0 = lrow0 * f0 + ts0;
        lrow1 = lrow1 * f1 + ts1;

        // ---- apply mask * diag, store P (tf32) to per-warp smem strip ----
        const float* mp0 = mr0 + kt*64 + 2*lr;
        const float* mp1 = mr1 + kt*64 + 2*lr;
        #pragma unroll
        for (int j = 0; j < 8; j++) {
            float2 mk0 = *(const float2*)(mp0 + j*8);
            float2 mk1 = *(const float2*)(mp1 + j*8);
            float2 dg2 = *(const float2*)(ds + j*8 + 2*lr);
            float2 p0, p1;
            p0.x = __uint_as_float(f2tf(sacc[j][0] * mk0.x * dg2.x));
            p0.y = __uint_as_float(f2tf(sacc[j][1] * mk0.y * dg2.y));
            p1.x = __uint_as_float(f2tf(sacc[j][2] * mk1.x * dg2.x));
            p1.y = __uint_as_float(f2tf(sacc[j][3] * mk1.y * dg2.y));
            *(float2*)(Ps + (m0 + lq)*PSTRIDE + j*8 + 2*lr)     = p0;
            *(float2*)(Ps + (m0 + lq + 8)*PSTRIDE + j*8 + 2*lr) = p1;
        }

        // rescale O accumulator
        #pragma unroll
        for (int j = 0; j < 8; j++) {
            oacc[j][0] *= f0; oacc[j][1] *= f0;
            oacc[j][2] *= f1; oacc[j][3] *= f1;
        }
        __syncwarp();

        // ---- O += P @ V (tf32 MMA) ----
        #pragma unroll
        for (int k = 0; k < 8; k++) {
            unsigned a[4];
            int ab = (m0 + lq)*PSTRIDE + k*8 + lr;
            a[0] = __float_as_uint(Ps[ab]);
            a[1] = __float_as_uint(Ps[ab + 8*PSTRIDE]);
            a[2] = __float_as_uint(Ps[ab + 4]);
            a[3] = __float_as_uint(Ps[ab + 8*PSTRIDE + 4]);
            #pragma unroll
            for (int j2 = 0; j2 < 8; j2++) {
                int vb = (k*8 + lr)*VSTRIDE + j2*8 + lq;
                unsigned b0 = __float_as_uint(Vs[vb]);
                unsigned b1 = __float_as_uint(Vs[vb + 4*VSTRIDE]);
                mma_tf32(oacc[j2], a, b0, b1);
            }
        }
    }

    // ---- epilogue: O = acc / l ----
    float inv0 = 1.f / lrow0;
    float inv1 = 1.f / lrow1;
    const int r0 = q0 + m0 + lq;
    const int r1 = r0 + 8;
    #pragma unroll
    for (int j2 = 0; j2 < 8; j2++) {
        int c = h*HD_ + j2*8 + 2*lr;
        float2 o0; o0.x = oacc[j2][0]*inv0; o0.y = oacc[j2][1]*inv0;
        float2 o1; o1.x = oacc[j2][2]*inv1; o1.y = oacc[j2][3]*inv1;
        *(float2*)(out + ((size_t)b*NQ_ + r0)*DM_ + c) = o0;
        *(float2*)(out + ((size_t)b*NQ_ + r1)*DM_ + c) = o1;
    }
}

// ---------------------------------------------------------------------------
#define ATTN_SMEM ((64*KSTRIDE + 64*VSTRIDE + 128*PSTRIDE + 64) * (int)sizeof(float))
#define PROJ_SMEM ((128*KSTRIDE + 64*KSTRIDE) * (int)sizeof(float))

extern "C" void kernel_launch(void* const* d_in, const int* in_sizes, int n_in,
                              void* d_out, int out_size)
{
    const float* q       = (const float*)d_in[0];
    const float* k       = (const float*)d_in[1];
    const float* v       = (const float*)d_in[2];
    const float* mask    = (const float*)d_in[3];
    const float* pearson = (const float*)d_in[4];
    const float* Wq      = (const float*)d_in[5];
    const float* bq      = (const float*)d_in[6];
    const float* Wk      = (const float*)d_in[7];
    const float* bk      = (const float*)d_in[8];
    const float* Wv      = (const float*)d_in[9];
    const float* bv      = (const float*)d_in[10];
    float* out = (float*)d_out;

    cudaFuncSetAttribute(attn_kernel,
                         cudaFuncAttributeMaxDynamicSharedMemorySize, ATTN_SMEM);
    cudaFuncSetAttribute(proj_kernel,
                         cudaFuncAttributeMaxDynamicSharedMemorySize, PROJ_SMEM);

    dim3 pg(DM_/64, (B_*NQ_)/128, 3);
    proj_kernel<<<pg, 256, PROJ_SMEM>>>(q, k, v, Wq, bq, Wk, bk, Wv, bv);

    diag_kernel<<<(B_*H_*NK_ + 255)/256, 256>>>(pearson);

    dim3 ag(NQ_/128, H_, B_);
    attn_kernel<<<ag, 256, ATTN_SMEM>>>(mask, out);
}

// round 6
// speedup vs baseline: 5.8960x; 1.7718x over previous
#include <cuda_runtime.h>
#include <cuda_fp16.h>
#include <math.h>
#include <stdint.h>

#define B_   2
#define H_   8
#define NQ_  2048
#define NK_  2048
#define DM_  512
#define HD_  64
#define EXP2C 0.18033688011112042f   /* 0.125 * log2(e) */

#define SH2 36   // half2 words per 64-half row (32 data + 4 pad); 36%32==4 -> conflict-free frags

// Scratch (allocation-free rule: __device__ globals) — fp16 Q/K/V
__device__ __half g_Q[B_*H_*NQ_*HD_];
__device__ __half g_K[B_*H_*NK_*HD_];
__device__ __half g_V[B_*H_*NK_*HD_];
__device__ float  g_diag[B_*H_*NK_];

// ---------------------------------------------------------------------------
// helpers
// ---------------------------------------------------------------------------
__device__ __forceinline__ float fast_ex2(float x) {
    float y;
    asm("ex2.approx.ftz.f32 %0, %1;" : "=f"(y) : "f"(x));
    return y;
}
__device__ __forceinline__ uint32_t f2h2(float lo, float hi) {
    __half2 h = __floats2half2_rn(lo, hi);
    return *reinterpret_cast<uint32_t*>(&h);
}
__device__ __forceinline__ void mma_f16(float c[4], const uint32_t a[4],
                                        uint32_t b0, uint32_t b1) {
    asm volatile(
        "mma.sync.aligned.m16n8k16.row.col.f32.f16.f16.f32 "
        "{%0,%1,%2,%3}, {%4,%5,%6,%7}, {%8,%9}, {%0,%1,%2,%3};\n"
        : "+f"(c[0]), "+f"(c[1]), "+f"(c[2]), "+f"(c[3])
        : "r"(a[0]), "r"(a[1]), "r"(a[2]), "r"(a[3]), "r"(b0), "r"(b1));
}
__device__ __forceinline__ void ldsm_x4_t(uint32_t r[4], uint32_t addr) {
    asm volatile(
        "ldmatrix.sync.aligned.m8n8.x4.trans.shared.b16 {%0,%1,%2,%3}, [%4];"
        : "=r"(r[0]), "=r"(r[1]), "=r"(r[2]), "=r"(r[3]) : "r"(addr));
}
__device__ __forceinline__ uint32_t smem_u32(const void* p) {
    uint32_t a;
    asm("{ .reg .u64 t; cvta.to.shared.u64 t, %1; cvt.u32.u64 %0, t; }"
        : "=r"(a) : "l"(p));
    return a;
}

// ---------------------------------------------------------------------------
// Projection via fp16 m16n8k16 MMA; writes fp16 head-major scratch.
// grid (DM/64, B*N/128, 3); block 256 (8 warps x 16 rows)
// ---------------------------------------------------------------------------
__global__ __launch_bounds__(256) void proj_kernel(
    const float* __restrict__ q, const float* __restrict__ k,
    const float* __restrict__ v,
    const float* __restrict__ Wq, const float* __restrict__ bq,
    const float* __restrict__ Wk, const float* __restrict__ bk,
    const float* __restrict__ Wv, const float* __restrict__ bv)
{
    extern __shared__ uint32_t smu[];
    uint32_t* Xs = smu;                 // 128 x SH2 half2
    uint32_t* Ws = Xs + 128*SH2;        // 64  x SH2 half2

    const float *X, *W, *bias;
    __half* outp;
    if (blockIdx.z == 0)      { X = q; W = Wq; bias = bq; outp = g_Q; }
    else if (blockIdx.z == 1) { X = k; W = Wk; bias = bk; outp = g_K; }
    else                      { X = v; W = Wv; bias = bv; outp = g_V; }

    const int tid  = threadIdx.x;
    const int lane = tid & 31, warp = tid >> 5;
    const int lq = lane >> 2, lr = lane & 3;
    const int m0 = warp * 16;
    const int row0 = blockIdx.y * 128;
    const int col0 = blockIdx.x * 64;

    float acc[8][4];
    #pragma unroll
    for (int j = 0; j < 8; j++)
        #pragma unroll
        for (int i = 0; i < 4; i++) acc[j][i] = 0.f;

    for (int kc = 0; kc < DM_; kc += 64) {
        #pragma unroll
        for (int it = 0; it < 8; it++) {
            int idx = tid + it * 256;
            int r = idx >> 4, c4 = (idx & 15) << 2;
            float4 xv = *(const float4*)(X + (size_t)(row0 + r) * DM_ + kc + c4);
            Xs[r*SH2 + (c4 >> 1)]     = f2h2(xv.x, xv.y);
            Xs[r*SH2 + (c4 >> 1) + 1] = f2h2(xv.z, xv.w);
        }
        #pragma unroll
        for (int it = 0; it < 4; it++) {
            int idx = tid + it * 256;
            int n = idx >> 4, c4 = (idx & 15) << 2;
            float4 wv = *(const float4*)(W + (size_t)(col0 + n) * DM_ + kc + c4);
            Ws[n*SH2 + (c4 >> 1)]     = f2h2(wv.x, wv.y);
            Ws[n*SH2 + (c4 >> 1) + 1] = f2h2(wv.z, wv.w);
        }
        __syncthreads();

        #pragma unroll
        for (int kk = 0; kk < 4; kk++) {
            uint32_t a[4];
            int ab = (m0 + lq)*SH2 + kk*8 + lr;
            a[0] = Xs[ab];
            a[1] = Xs[ab + 8*SH2];
            a[2] = Xs[ab + 4];
            a[3] = Xs[ab + 8*SH2 + 4];
            #pragma unroll
            for (int j = 0; j < 8; j++) {
                int bb = (j*8 + lq)*SH2 + kk*8 + lr;
                mma_f16(acc[j], a, Ws[bb], Ws[bb + 4]);
            }
        }
        __syncthreads();
    }

    // epilogue: bias, cvt fp16, scatter head-major
    const int r0g = row0 + m0 + lq;
    const int r1g = r0g + 8;
    #pragma unroll
    for (int j = 0; j < 8; j++) {
        int jj = col0 + j*8 + 2*lr;
        float2 bs = *(const float2*)(bias + jj);
        int h = jj >> 6, d = jj & 63;
        {
            int b = r0g >> 11, n = r0g & 2047;
            uint32_t o = f2h2(acc[j][0] + bs.x, acc[j][1] + bs.y);
            *(uint32_t*)(outp + (((size_t)(b*H_ + h) * NQ_) + n) * HD_ + d) = o;
        }
        {
            int b = r1g >> 11, n = r1g & 2047;
            uint32_t o = f2h2(acc[j][2] + bs.x, acc[j][3] + bs.y);
            *(uint32_t*)(outp + (((size_t)(b*H_ + h) * NQ_) + n) * HD_ + d) = o;
        }
    }
}

// ---------------------------------------------------------------------------
// diag extraction
// ---------------------------------------------------------------------------
__global__ void diag_kernel(const float* __restrict__ pearson)
{
    int idx = blockIdx.x * 256 + threadIdx.x;
    if (idx < B_*H_*NK_) {
        int k  = idx & (NK_ - 1);
        int bh = idx >> 11;
        g_diag[idx] = pearson[((size_t)bh * NK_ + k) * NK_ + k];
    }
}

// ---------------------------------------------------------------------------
// Fused attention, fp16 m16n8k16 MMA, fixed-base softmax (no running max).
// 256 threads (8 warps), 128 q-rows per CTA; 64-key tiles.
// grid (NQ/128, H, B)
// ---------------------------------------------------------------------------
#define ATTN_SMEM ((64*SH2 + 64*SH2 + 128*SH2) * 4 + 64 * 4)

__global__ __launch_bounds__(256) void attn_kernel(
    const float* __restrict__ mask, float* __restrict__ out)
{
    extern __shared__ uint32_t smu[];
    uint32_t* Ks = smu;                    // 64  x SH2 (K[n][d] half2)
    uint32_t* Vs = Ks + 64*SH2;            // 64  x SH2 (V[k][d] half2)
    uint32_t* Ps = Vs + 64*SH2;            // 128 x SH2 (Q staging, then P)
    float*    ds = (float*)(Ps + 128*SH2); // 64 diag

    const int tid  = threadIdx.x;
    const int lane = tid & 31, warp = tid >> 5;
    const int lq = lane >> 2, lr = lane & 3;
    const int m0 = warp * 16;
    const int q0 = blockIdx.x * 128;
    const int h  = blockIdx.y;
    const int b  = blockIdx.z;
    const int bh = b * H_ + h;

    const __half* Qg = g_Q + (size_t)bh * NQ_ * HD_ + (size_t)q0 * HD_;
    const __half* Kg = g_K + (size_t)bh * NK_ * HD_;
    const __half* Vg = g_V + (size_t)bh * NK_ * HD_;
    const float*  dg = g_diag + (size_t)bh * NK_;
    const float*  mg = mask + ((size_t)bh * NQ_ + q0) * NK_;

    // ---- stage Q into Ps (raw fp16 copy), extract persistent A-frags ----
    #pragma unroll
    for (int it = 0; it < 4; it++) {
        int e = it*256 + tid;
        int r = e >> 3, c8 = (e & 7) << 3;
        *(uint4*)&Ps[r*SH2 + (c8 >> 1)] = *(const uint4*)(Qg + (size_t)r * HD_ + c8);
    }
    __syncthreads();

    uint32_t qf[4][4];
    #pragma unroll
    for (int kk = 0; kk < 4; kk++) {
        int ab = (m0 + lq)*SH2 + kk*8 + lr;
        qf[kk][0] = Ps[ab];
        qf[kk][1] = Ps[ab + 8*SH2];
        qf[kk][2] = Ps[ab + 4];
        qf[kk][3] = Ps[ab + 8*SH2 + 4];
    }

    // ldmatrix lane base for V (rows k, cols d)
    const uint32_t vs_base = smem_u32(Vs)
                           + (uint32_t)(lane & 15) * (SH2*4)
                           + (uint32_t)(lane >> 4) * 16;

    float lsum0 = 0.f, lsum1 = 0.f;
    float oacc[8][4];
    #pragma unroll
    for (int j = 0; j < 8; j++)
        #pragma unroll
        for (int i = 0; i < 4; i++) oacc[j][i] = 0.f;

    const float* mr0 = mg + (size_t)(m0 + lq) * NK_ + 2*lr;
    const float* mr1 = mr0 + (size_t)8 * NK_;

    for (int kt = 0; kt < NK_/64; kt++) {
        __syncthreads();   // prior-tile PV reads of Ks/Vs/Ps done

        // ---- stage K and V tiles (raw fp16 uint4 copies) + diag ----
        const __half* Kt = Kg + (size_t)kt * 64 * HD_;
        const __half* Vt = Vg + (size_t)kt * 64 * HD_;
        #pragma unroll
        for (int it = 0; it < 2; it++) {
            int e = it*256 + tid;
            int r = e >> 3, c8 = (e & 7) << 3;
            *(uint4*)&Ks[r*SH2 + (c8 >> 1)] = *(const uint4*)(Kt + (size_t)r * HD_ + c8);
            *(uint4*)&Vs[r*SH2 + (c8 >> 1)] = *(const uint4*)(Vt + (size_t)r * HD_ + c8);
        }
        if (tid < 16) ((float4*)ds)[tid] = ((const float4*)(dg + kt*64))[tid];
        __syncthreads();

        // ---- S = Q @ K^T ----
        float sacc[8][4];
        #pragma unroll
        for (int j = 0; j < 8; j++)
            #pragma unroll
            for (int i = 0; i < 4; i++) sacc[j][i] = 0.f;

        #pragma unroll
        for (int kk = 0; kk < 4; kk++) {
            #pragma unroll
            for (int j = 0; j < 8; j++) {
                int bb = (j*8 + lq)*SH2 + kk*8 + lr;
                mma_f16(sacc[j], qf[kk], Ks[bb], Ks[bb + 4]);
            }
        }

        // ---- fixed-base softmax + mask*diag, store P (fp16) ----
        const float* mp0 = mr0 + kt*64;
        const float* mp1 = mr1 + kt*64;
        #pragma unroll
        for (int j = 0; j < 8; j++) {
            float2 mk0 = *(const float2*)(mp0 + j*8);
            float2 mk1 = *(const float2*)(mp1 + j*8);
            float2 d2  = *(const float2*)(ds + j*8 + 2*lr);
            float p0 = fast_ex2(sacc[j][0] * EXP2C);
            float p1 = fast_ex2(sacc[j][1] * EXP2C);
            float p2 = fast_ex2(sacc[j][2] * EXP2C);
            float p3 = fast_ex2(sacc[j][3] * EXP2C);
            lsum0 += p0 + p1;
            lsum1 += p2 + p3;
            Ps[(m0 + lq)*SH2 + j*4 + lr]     = f2h2(p0 * mk0.x * d2.x, p1 * mk0.y * d2.y);
            Ps[(m0 + lq + 8)*SH2 + j*4 + lr] = f2h2(p2 * mk1.x * d2.x, p3 * mk1.y * d2.y);
        }
        __syncwarp();   // P strip is warp-private; make writes visible in-warp

        // ---- O += P @ V ----
        #pragma unroll
        for (int kk = 0; kk < 4; kk++) {
            uint32_t pa[4];
            int ab = (m0 + lq)*SH2 + kk*8 + lr;
            pa[0] = Ps[ab];
            pa[1] = Ps[ab + 8*SH2];
            pa[2] = Ps[ab + 4];
            pa[3] = Ps[ab + 8*SH2 + 4];
            #pragma unroll
            for (int jp = 0; jp < 4; jp++) {
                uint32_t vb[4];
                ldsm_x4_t(vb, vs_base + (uint32_t)kk*(16*SH2*4) + (uint32_t)jp*32);
                mma_f16(oacc[2*jp],     pa, vb[0], vb[1]);
                mma_f16(oacc[2*jp + 1], pa, vb[2], vb[3]);
            }
        }
    }

    // ---- final l reduction over the quad (lr bits) and store ----
    lsum0 += __shfl_xor_sync(0xffffffffu, lsum0, 1);
    lsum0 += __shfl_xor_sync(0xffffffffu, lsum0, 2);
    lsum1 += __shfl_xor_sync(0xffffffffu, lsum1, 1);
    lsum1 += __shfl_xor_sync(0xffffffffu, lsum1, 2);
    float inv0 = 1.f / lsum0;
    float inv1 = 1.f / lsum1;

    const int r0 = q0 + m0 + lq;
    const int r1 = r0 + 8;
    #pragma unroll
    for (int j = 0; j < 8; j++) {
        int c = h*HD_ + j*8 + 2*lr;
        float2 o0; o0.x = oacc[j][0]*inv0; o0.y = oacc[j][1]*inv0;
        float2 o1; o1.x = oacc[j][2]*inv1; o1.y = oacc[j][3]*inv1;
        *(float2*)(out + ((size_t)b*NQ_ + r0)*DM_ + c) = o0;
        *(float2*)(out + ((size_t)b*NQ_ + r1)*DM_ + c) = o1;
    }
}

// ---------------------------------------------------------------------------
#define PROJ_SMEM ((128*SH2 + 64*SH2) * 4)

extern "C" void kernel_launch(void* const* d_in, const int* in_sizes, int n_in,
                              void* d_out, int out_size)
{
    const float* q       = (const float*)d_in[0];
    const float* k       = (const float*)d_in[1];
    const float* v       = (const float*)d_in[2];
    const float* mask    = (const float*)d_in[3];
    const float* pearson = (const float*)d_in[4];
    const float* Wq      = (const float*)d_in[5];
    const float* bq      = (const float*)d_in[6];
    const float* Wk      = (const float*)d_in[7];
    const float* bk      = (const float*)d_in[8];
    const float* Wv      = (const float*)d_in[9];
    const float* bv      = (const float*)d_in[10];
    float* out = (float*)d_out;

    cudaFuncSetAttribute(proj_kernel,
                         cudaFuncAttributeMaxDynamicSharedMemorySize, PROJ_SMEM);
    cudaFuncSetAttribute(attn_kernel,
                         cudaFuncAttributeMaxDynamicSharedMemorySize, ATTN_SMEM);

    dim3 pg(DM_/64, (B_*NQ_)/128, 3);
    proj_kernel<<<pg, 256, PROJ_SMEM>>>(q, k, v, Wq, bq, Wk, bk, Wv, bv);

    diag_kernel<<<(B_*H_*NK_ + 255)/256, 256>>>(pearson);

    dim3 ag(NQ_/128, H_, B_);
    attn_kernel<<<ag, 256, ATTN_SMEM>>>(mask, out);
}